// round 13
// baseline (speedup 1.0000x reference)
#include <cuda_runtime.h>
#include <float.h>

#define NB 32
#define NS 512
#define NH 1024
#define NCAND 256
#define NL 34
#define NCH 16
#define CSZ 32
#define SPLIT 8
#define KS 256                 // 2048/8 floats per gemm K-split
#define GRID 444               // 3 blocks/SM x 148 SMs, all co-resident
#define CMB (NB * NCH * 2)     // 1024 chunk cells
#define WTB 288                // W-transpose virtual blocks
#define PHA_TOT (CMB + WTB)    // 1312
#define PHB_TOT (NB * 2)       // 64 scan/combine cells (b x h-half)
#define PHC_TOT (32 * 9)       // 288 gemm tiles

// Scratch (__device__ globals; no allocation allowed)
__device__ float g_cmax[NB * NCH * NH];
__device__ float g_plp[NCAND * NH];
__device__ float g_prp[NCAND * NH];
__device__ float g_pooled[NCAND * 2 * NH];
__device__ float g_Wt[36 * 2 * NH];
// Sense-reversing grid barrier state. Ends each call as {GRID, 0} (2 barriers
// per call -> sense returns to 0), so graph replays see identical state.
__device__ int g_barcnt = GRID;
__device__ int g_sense = 0;

__device__ __forceinline__ float2 f2max(float2 a, float2 b) {
    float2 r;
    r.x = fmaxf(a.x, b.x);
    r.y = fmaxf(a.y, b.y);
    return r;
}

// ---------------------------------------------------------------------------
// Single persistent kernel: Phase A (chunk maxes + in-chunk candidate
// partials + W transpose) -> barrier -> Phase B (prefix/suffix over chunk
// maxes in registers, emit pooled) -> barrier -> Phase C (register-tiled
// gemm with in-block K-reduction).
// ---------------------------------------------------------------------------
__global__ __launch_bounds__(256, 3) void k_all(const float* __restrict__ hidden,
                                                const float* __restrict__ W,
                                                const float* __restrict__ bias,
                                                const int* __restrict__ cb,
                                                const int* __restrict__ cc,
                                                float* __restrict__ out) {
    __shared__ int s_cnt;
    __shared__ int s_n[NCAND];
    __shared__ int s_r[NCAND];
    __shared__ int s_sense;
    __shared__ float sp[SPLIT][32];

    int tid = threadIdx.x;
    if (tid == 0) s_sense = 0;
    __syncthreads();

    // ======================= Phase A =======================
    for (int vb = blockIdx.x; vb < PHA_TOT; vb += GRID) {
        if (vb >= CMB) {   // ---- W transpose slice ----
            int idx = (vb - CMB) * 256 + tid;
            int l = idx >> 11;
            int k = idx & (2 * NH - 1);
            g_Wt[idx] = (l < NL) ? W[(size_t)k * NL + l] : 0.f;
            continue;
        }
        int b = vb >> 5;
        int q = (vb >> 1) & 15;
        int hb = vb & 1;
        int h2 = hb * 256 + tid;    // float2 index within the 1024-float row

        const float2* base =
            (const float2*)(hidden + ((size_t)(b * NS + q * CSZ)) * NH) + h2;

        // Loads first: matching prologue executes under load latency.
        float2 v[CSZ];
#pragma unroll
        for (int k = 0; k < CSZ; k++) v[k] = __ldcs(&base[k * (NH / 2)]);

        __syncthreads();            // previous iteration done with s_cnt/s_n
        if (tid == 0) s_cnt = 0;
        __syncthreads();
        {
            int cn = cc[tid];       // tid in [0,256) == NCAND
            if (cb[tid] == b && (cn >> 5) == q) {
                int p = atomicAdd(&s_cnt, 1);
                s_n[p] = tid;
                s_r[p] = cn & 31;
            }
        }

        float2 m = make_float2(-FLT_MAX, -FLT_MAX);
#pragma unroll
        for (int k = 0; k < CSZ; k += 4) {
            float2 t0 = f2max(v[k], v[k + 1]);
            float2 t1 = f2max(v[k + 2], v[k + 3]);
            m = f2max(m, f2max(t0, t1));
        }
        ((float2*)(g_cmax + ((size_t)b * NCH + q) * NH))[h2] = m;

        __syncthreads();
        int cnt = s_cnt;
        for (int j = 0; j < cnt; j++) {
            int n = s_n[j];
            int r = s_r[j];
            float2 ml = make_float2(-FLT_MAX, -FLT_MAX);
            float2 mr = ml;
#pragma unroll
            for (int k = 0; k < CSZ; k++) {
                if (k < r) ml = f2max(ml, v[k]);
                else       mr = f2max(mr, v[k]);
            }
            ((float2*)(g_plp + (size_t)n * NH))[h2] = ml;
            ((float2*)(g_prp + (size_t)n * NH))[h2] = mr;
        }
    }

    // ---- grid barrier 1 ----
    __syncthreads();
    if (tid == 0) {
        int s = s_sense ^ 1;
        s_sense = s;
        __threadfence();
        if (atomicAdd(&g_barcnt, -1) == 1) {
            g_barcnt = GRID;        // reset for next use
            __threadfence();
            atomicExch(&g_sense, s);
        } else {
            while (atomicAdd(&g_sense, 0) != s) __nanosleep(64);
        }
    }
    __syncthreads();
    __threadfence();

    // ======================= Phase B =======================
    // vb = b*2 + h-half. Registers only: pref/suf via predicated fmax.
    for (int vb = blockIdx.x; vb < PHB_TOT; vb += GRID) {
        int b = vb >> 1;
        int hb = vb & 1;
        int h2 = hb * 256 + tid;

        const float2* cm = (const float2*)(g_cmax + (size_t)b * NCH * NH) + h2;
        float2 v[NCH];
#pragma unroll
        for (int q = 0; q < NCH; q++) v[q] = cm[q * (NH / 2)];

        __syncthreads();
        if (tid == 0) s_cnt = 0;
        __syncthreads();
        {
            if (cb[tid] == b) {
                int p = atomicAdd(&s_cnt, 1);
                s_n[p] = tid;
                s_r[p] = cc[tid] >> 5;
            }
        }
        __syncthreads();
        int cnt = s_cnt;
        for (int j = 0; j < cnt; j++) {
            int n = s_n[j];
            int qj = s_r[j];
            float2 pl = make_float2(-FLT_MAX, -FLT_MAX);
            float2 pr = pl;
#pragma unroll
            for (int q = 0; q < NCH; q++) {
                if (q < qj) pl = f2max(pl, v[q]);
                if (q > qj) pr = f2max(pr, v[q]);
            }
            pl = f2max(pl, ((const float2*)(g_plp + (size_t)n * NH))[h2]);
            pr = f2max(pr, ((const float2*)(g_prp + (size_t)n * NH))[h2]);
            ((float2*)(g_pooled + (size_t)n * (2 * NH)))[h2] = pl;
            ((float2*)(g_pooled + (size_t)n * (2 * NH) + NH))[h2] = pr;
        }
    }

    // ---- grid barrier 2 ----
    __syncthreads();
    if (tid == 0) {
        int s = s_sense ^ 1;
        s_sense = s;
        __threadfence();
        if (atomicAdd(&g_barcnt, -1) == 1) {
            g_barcnt = GRID;
            __threadfence();
            atomicExch(&g_sense, s);
        } else {
            while (atomicAdd(&g_sense, 0) != s) __nanosleep(64);
        }
    }
    __syncthreads();
    __threadfence();

    // ======================= Phase C =======================
    // vb = co*9 + lq; 8 warps = K-splits of one output tile, reduce in smem.
    for (int vb = blockIdx.x; vb < PHC_TOT; vb += GRID) {
        int co = vb / 9;
        int lq = vb - co * 9;
        int wid = tid >> 5;
        int lane = tid & 31;
        int kbase = wid * KS;

        const float4* A = (const float4*)(g_pooled + (size_t)(co * 8) * (2 * NH) + kbase);
        const float4* Wt = (const float4*)(g_Wt + (size_t)(lq * 4) * (2 * NH) + kbase);
        const int rs = (2 * NH) / 4;

        float acc[8][4];
#pragma unroll
        for (int c = 0; c < 8; c++)
#pragma unroll
            for (int l = 0; l < 4; l++) acc[c][l] = 0.f;

#pragma unroll
        for (int step = 0; step < KS / 128; step++) {
            int i = lane + step * 32;
            float4 a[8], w[4];
#pragma unroll
            for (int c = 0; c < 8; c++) a[c] = A[c * rs + i];
#pragma unroll
            for (int l = 0; l < 4; l++) w[l] = Wt[l * rs + i];
#pragma unroll
            for (int c = 0; c < 8; c++)
#pragma unroll
                for (int l = 0; l < 4; l++) {
                    acc[c][l] += a[c].x * w[l].x;
                    acc[c][l] += a[c].y * w[l].y;
                    acc[c][l] += a[c].z * w[l].z;
                    acc[c][l] += a[c].w * w[l].w;
                }
        }

#pragma unroll
        for (int c = 0; c < 8; c++)
#pragma unroll
            for (int l = 0; l < 4; l++) {
                float s = acc[c][l];
#pragma unroll
                for (int o = 16; o; o >>= 1) s += __shfl_xor_sync(0xffffffffu, s, o);
                if (lane == 0) sp[wid][c * 4 + l] = s;
            }
        __syncthreads();

        if (tid < 32) {
            int c = tid >> 2;
            int l = tid & 3;
            int label = lq * 4 + l;
            if (label < NL) {
                float s = bias[label];
#pragma unroll
                for (int w = 0; w < SPLIT; w++) s += sp[w][tid];
                out[(size_t)(co * 8 + c) * NL + label] = s;
            }
        }
        __syncthreads();   // sp reuse safety if a block ever takes 2 tiles
    }
}

// ---------------------------------------------------------------------------
extern "C" void kernel_launch(void* const* d_in, const int* in_sizes, int n_in,
                              void* d_out, int out_size) {
    const float* hidden = (const float*)d_in[0];
    const float* W = (const float*)d_in[1];
    const float* bias = (const float*)d_in[2];
    const int* cb = (const int*)d_in[3];
    const int* cc = (const int*)d_in[4];
    float* out = (float*)d_out;

    k_all<<<GRID, 256>>>(hidden, W, bias, cb, cc, out);
}

// round 14
// speedup vs baseline: 1.1825x; 1.1825x over previous
#include <cuda_runtime.h>
#include <float.h>

#define NB 32
#define NS 512
#define NH 1024
#define NCAND 256
#define NL 34
#define NHC 32      // half-chunks per sequence
#define HSZ 16      // tokens per half-chunk
#define SPLIT 8     // K-split (warps per gemm block)
#define KS (2 * NH / SPLIT)   // 256 floats per split
#define CMB (NB * NHC)        // 1024 half-chunk cells
#define WTB 288               // wt blocks (288*256 = 36*2048)

// Scratch (__device__ globals; no allocation allowed)
__device__ float g_cmax[NB * NHC * NH];          // 4 MB half-chunk maxes
__device__ float g_plp[NCAND * NH];
__device__ float g_prp[NCAND * NH];
__device__ float g_pooled[NCAND * 2 * NH];
__device__ float g_Wt[36 * 2 * NH];              // W transposed+padded [36][2048]

__device__ __forceinline__ float4 f4max(float4 a, float4 b) {
    float4 r;
    r.x = fmaxf(a.x, b.x);
    r.y = fmaxf(a.y, b.y);
    r.z = fmaxf(a.z, b.z);
    r.w = fmaxf(a.w, b.w);
    return r;
}

// ---------------------------------------------------------------------------
// Kernel A: per-(b, half-chunk) maxes. Thread owns 4 h via LDG.128 (512 B
// per warp-instruction -> 2x bytes per outstanding LDG vs float2; the SM-wide
// outstanding-LDG cap ~64 is the DRAM limiter). v[16] float4 = 64 payload
// regs keeps total ~80 -> 3 blocks/SM (round-9's v[32] float4 hit 152 regs /
// 1 block/SM and lost the duty cycle). Loads issue FIRST; candidate matching
// runs under their latency. Candidate in-half-chunk partials are race-free
// (the cut's half-chunk owns both partials, r = c & 15).
// W transpose rides along as trailing blocks.
// ---------------------------------------------------------------------------
__global__ __launch_bounds__(256, 3) void k_A(const float* __restrict__ hidden,
                                              const float* __restrict__ W,
                                              const int* __restrict__ cb,
                                              const int* __restrict__ cc) {
    int bid = blockIdx.x;
    int tid = threadIdx.x;

    if (bid >= CMB) {   // ---- W transpose part ----
        int idx = (bid - CMB) * 256 + tid;
        int l = idx >> 11;
        int k = idx & (2 * NH - 1);
        g_Wt[idx] = (l < NL) ? W[(size_t)k * NL + l] : 0.f;
        return;
    }

    // ---- half-chunk cell: b = bid>>5, hq = bid&31; thread owns 4 h ----
    __shared__ int s_cnt;
    __shared__ int s_n[NCAND];
    __shared__ int s_r[NCAND];

    int b = bid >> 5;
    int hq = bid & 31;

    const float4* base =
        (const float4*)(hidden + ((size_t)(b * NS + hq * HSZ)) * NH) + tid;
    const int rs4 = NH / 4;         // token stride in float4

    // ---- loads FIRST: 16 LDG.128 front-batched before any sync ----
    float4 v[HSZ];
#pragma unroll
    for (int k = 0; k < HSZ; k++) v[k] = __ldcs(&base[k * rs4]);

    // ---- candidate matching overlaps the load latency ----
    if (tid == 0) s_cnt = 0;
    __syncthreads();
    {
        int cn = cc[tid];           // tid in [0,256) == NCAND
        if (cb[tid] == b && (cn >> 4) == hq) {
            int p = atomicAdd(&s_cnt, 1);
            s_n[p] = tid;
            s_r[p] = cn & 15;
        }
    }

    // Pairwise tree reduce.
    float4 m = make_float4(-FLT_MAX, -FLT_MAX, -FLT_MAX, -FLT_MAX);
#pragma unroll
    for (int k = 0; k < HSZ; k += 4) {
        float4 t0 = f4max(v[k], v[k + 1]);
        float4 t1 = f4max(v[k + 2], v[k + 3]);
        m = f4max(m, f4max(t0, t1));
    }
    ((float4*)(g_cmax + ((size_t)b * NHC + hq) * NH))[tid] = m;

    __syncthreads();
    int cnt = s_cnt;
    for (int j = 0; j < cnt; j++) {
        int n = s_n[j];
        int r = s_r[j];
        float4 ml = make_float4(-FLT_MAX, -FLT_MAX, -FLT_MAX, -FLT_MAX);
        float4 mr = ml;
#pragma unroll
        for (int k = 0; k < HSZ; k++) {
            if (k < r) ml = f4max(ml, v[k]);
            else       mr = f4max(mr, v[k]);
        }
        ((float4*)(g_plp + (size_t)n * NH))[tid] = ml;
        ((float4*)(g_prp + (size_t)n * NH))[tid] = mr;
    }
}

// ---------------------------------------------------------------------------
// Kernel B: prefix/suffix max over the 32 half-chunk maxes (registers,
// predicated — no large smem), emit pooled per candidate.
// ---------------------------------------------------------------------------
__global__ void k_scan_combine(const int* __restrict__ cb,
                               const int* __restrict__ cc) {
    __shared__ int s_cnt;
    __shared__ int s_n[NCAND];
    __shared__ int s_q[NCAND];

    int tid = threadIdx.x;
    int h = blockIdx.x * 256 + tid;
    int b = blockIdx.y;

    if (tid == 0) s_cnt = 0;
    __syncthreads();
    if (cb[tid] == b) {
        int p = atomicAdd(&s_cnt, 1);
        s_n[p] = tid;
        s_q[p] = cc[tid] >> 4;      // owning half-chunk
    }

    const float* cm = g_cmax + (size_t)b * NHC * NH + h;
    float v[NHC];
#pragma unroll
    for (int q = 0; q < NHC; q++) v[q] = cm[(size_t)q * NH];

    __syncthreads();
    int cnt = s_cnt;
    for (int j = 0; j < cnt; j++) {
        int n = s_n[j];
        int qj = s_q[j];
        float pl = -FLT_MAX, pr = -FLT_MAX;
#pragma unroll
        for (int q = 0; q < NHC; q++) {
            if (q < qj) pl = fmaxf(pl, v[q]);
            if (q > qj) pr = fmaxf(pr, v[q]);
        }
        pl = fmaxf(pl, g_plp[(size_t)n * NH + h]);
        pr = fmaxf(pr, g_prp[(size_t)n * NH + h]);
        g_pooled[(size_t)n * (2 * NH) + h] = pl;
        g_pooled[(size_t)n * (2 * NH) + NH + h] = pr;
    }
}

// ---------------------------------------------------------------------------
// Kernel C: gemm with fused reduction. Block = (cand-oct, label-quad),
// 8 warps = K-splits of the SAME output tile; K-reduction completes in smem
// and writes out directly. Lane holds 8 A-float4 + 4 W-float4 per step.
// ---------------------------------------------------------------------------
__global__ __launch_bounds__(256) void k_gemm(const float* __restrict__ bias,
                                              float* __restrict__ out) {
    __shared__ float sp[SPLIT][32];
    int wid = threadIdx.x >> 5;     // K-split 0..7
    int lane = threadIdx.x & 31;
    int co = blockIdx.x;            // cand-oct 0..31
    int lq = blockIdx.y;            // label-quad 0..8
    int kbase = wid * KS;

    const float4* A = (const float4*)(g_pooled + (size_t)(co * 8) * (2 * NH) + kbase);
    const float4* Wt = (const float4*)(g_Wt + (size_t)(lq * 4) * (2 * NH) + kbase);
    const int rs = (2 * NH) / 4;

    float acc[8][4];
#pragma unroll
    for (int c = 0; c < 8; c++)
#pragma unroll
        for (int l = 0; l < 4; l++) acc[c][l] = 0.f;

#pragma unroll
    for (int step = 0; step < KS / 128; step++) {
        int i = lane + step * 32;
        float4 a[8], w[4];
#pragma unroll
        for (int c = 0; c < 8; c++) a[c] = A[c * rs + i];
#pragma unroll
        for (int l = 0; l < 4; l++) w[l] = Wt[l * rs + i];
#pragma unroll
        for (int c = 0; c < 8; c++)
#pragma unroll
            for (int l = 0; l < 4; l++) {
                acc[c][l] += a[c].x * w[l].x;
                acc[c][l] += a[c].y * w[l].y;
                acc[c][l] += a[c].z * w[l].z;
                acc[c][l] += a[c].w * w[l].w;
            }
    }

#pragma unroll
    for (int c = 0; c < 8; c++)
#pragma unroll
        for (int l = 0; l < 4; l++) {
            float s = acc[c][l];
#pragma unroll
            for (int o = 16; o; o >>= 1) s += __shfl_xor_sync(0xffffffffu, s, o);
            if (lane == 0) sp[wid][c * 4 + l] = s;
        }
    __syncthreads();

    if (threadIdx.x < 32) {
        int c = threadIdx.x >> 2;
        int l = threadIdx.x & 3;
        int label = lq * 4 + l;
        if (label < NL) {
            float s = bias[label];
#pragma unroll
            for (int w = 0; w < SPLIT; w++) s += sp[w][threadIdx.x];
            out[(size_t)(co * 8 + c) * NL + label] = s;
        }
    }
}

// ---------------------------------------------------------------------------
extern "C" void kernel_launch(void* const* d_in, const int* in_sizes, int n_in,
                              void* d_out, int out_size) {
    const float* hidden = (const float*)d_in[0];
    const float* W = (const float*)d_in[1];
    const float* bias = (const float*)d_in[2];
    const int* cb = (const int*)d_in[3];
    const int* cc = (const int*)d_in[4];
    float* out = (float*)d_out;

    k_A<<<CMB + WTB, 256>>>(hidden, W, cb, cc);

    dim3 gB(NH / 256, NB);
    k_scan_combine<<<gB, 256>>>(cb, cc);

    dim3 gC(32, 9);
    k_gemm<<<gC, 256>>>(bias, out);
}

// round 15
// speedup vs baseline: 1.1951x; 1.0107x over previous
#include <cuda_runtime.h>
#include <float.h>

#define NB 32
#define NS 512
#define NH 1024
#define NCAND 256
#define NL 34
#define NCH 16      // chunks per sequence
#define CSZ 32      // tokens per chunk
#define SPLIT 8     // K-split (warps per gemm block)
#define KS (2 * NH / SPLIT)   // 256 floats per split
#define CMB (NB * NCH * 2)    // 1024 chunk cells (2 h-halves of 512 floats)
#define WTB 288               // wt blocks (288*256 = 36*2048)

// Scratch (__device__ globals; no allocation allowed)
__device__ float g_cmax[NB * NCH * NH];
__device__ float g_plp[NCAND * NH];
__device__ float g_prp[NCAND * NH];
__device__ float g_pooled[NCAND * 2 * NH];
__device__ float g_Wt[36 * 2 * NH];              // W transposed+padded [36][2048]

__device__ __forceinline__ float2 f2max(float2 a, float2 b) {
    float2 r;
    r.x = fmaxf(a.x, b.x);
    r.y = fmaxf(a.y, b.y);
    return r;
}

// ---------------------------------------------------------------------------
// Kernel A (round-12 proven config, 13.9 us / 61.9% DRAM): per-(b,q,h-half)
// chunk maxes. Thread owns 2 h via float2, keeps all 32 tokens register-
// resident, ISSUES LOADS FIRST (candidate matching executes under load
// latency), __ldcs streaming so hidden doesn't thrash L2. 32 outstanding
// LDG.64 per thread is the empirically best in-flight configuration
// (beats 16x LDG.128 at equal bytes — round 14). W transpose rides along.
// ---------------------------------------------------------------------------
__global__ __launch_bounds__(256, 3) void k_A(const float* __restrict__ hidden,
                                              const float* __restrict__ W,
                                              const int* __restrict__ cb,
                                              const int* __restrict__ cc) {
    int bid = blockIdx.x;
    int tid = threadIdx.x;

    if (bid >= CMB) {   // ---- W transpose part ----
        int idx = (bid - CMB) * 256 + tid;
        int l = idx >> 11;
        int k = idx & (2 * NH - 1);
        g_Wt[idx] = (l < NL) ? W[(size_t)k * NL + l] : 0.f;
        return;
    }

    // ---- chunk cell: bid = b*32 + q*2 + hb; thread owns 2 h ----
    __shared__ int s_cnt;
    __shared__ int s_n[NCAND];
    __shared__ int s_r[NCAND];

    int b = bid >> 5;
    int q = (bid >> 1) & 15;
    int hb = bid & 1;
    int h2 = hb * 256 + tid;        // float2 index within the 1024-float row

    const float2* base =
        (const float2*)(hidden + ((size_t)(b * NS + q * CSZ)) * NH) + h2;
    const int rs2 = NH / 2;         // token stride in float2

    // ---- loads FIRST: 32 LDG.64 front-batched before any sync ----
    float2 v[CSZ];
#pragma unroll
    for (int k = 0; k < CSZ; k++) v[k] = __ldcs(&base[k * rs2]);

    // ---- candidate matching overlaps the load latency ----
    if (tid == 0) s_cnt = 0;
    __syncthreads();
    {
        int cn = cc[tid];           // tid in [0,256) == NCAND
        if (cb[tid] == b && (cn >> 5) == q) {
            int p = atomicAdd(&s_cnt, 1);
            s_n[p] = tid;
            s_r[p] = cn & 31;
        }
    }

    // Pairwise tree reduce (short dependency chains).
    float2 m = make_float2(-FLT_MAX, -FLT_MAX);
#pragma unroll
    for (int k = 0; k < CSZ; k += 4) {
        float2 t0 = f2max(v[k], v[k + 1]);
        float2 t1 = f2max(v[k + 2], v[k + 3]);
        m = f2max(m, f2max(t0, t1));
    }
    ((float2*)(g_cmax + ((size_t)b * NCH + q) * NH))[h2] = m;

    __syncthreads();
    int cnt = s_cnt;
    for (int j = 0; j < cnt; j++) {
        int n = s_n[j];
        int r = s_r[j];
        float2 ml = make_float2(-FLT_MAX, -FLT_MAX);
        float2 mr = ml;
#pragma unroll
        for (int k = 0; k < CSZ; k++) {
            if (k < r) ml = f2max(ml, v[k]);
            else       mr = f2max(mr, v[k]);
        }
        ((float2*)(g_plp + (size_t)n * NH))[h2] = ml;
        ((float2*)(g_prp + (size_t)n * NH))[h2] = mr;
    }
}

// ---------------------------------------------------------------------------
// Kernel B: register-predicated prefix/suffix over the 16 chunk maxes
// (no big smem arrays — round-14's leaner form), float2 throughout.
// Grid 64 cells (b x h-half) x 256 threads.
// ---------------------------------------------------------------------------
__global__ void k_scan_combine(const int* __restrict__ cb,
                               const int* __restrict__ cc) {
    __shared__ int s_cnt;
    __shared__ int s_n[NCAND];
    __shared__ int s_q[NCAND];

    int tid = threadIdx.x;
    int b = blockIdx.x >> 1;
    int hb = blockIdx.x & 1;
    int h2 = hb * 256 + tid;        // float2 index

    const float2* cm = (const float2*)(g_cmax + (size_t)b * NCH * NH) + h2;
    float2 v[NCH];
#pragma unroll
    for (int q = 0; q < NCH; q++) v[q] = cm[q * (NH / 2)];

    if (tid == 0) s_cnt = 0;
    __syncthreads();
    if (cb[tid] == b) {
        int p = atomicAdd(&s_cnt, 1);
        s_n[p] = tid;
        s_q[p] = cc[tid] >> 5;      // owning chunk
    }
    __syncthreads();

    int cnt = s_cnt;
    for (int j = 0; j < cnt; j++) {
        int n = s_n[j];
        int qj = s_q[j];
        float2 pl = make_float2(-FLT_MAX, -FLT_MAX);
        float2 pr = pl;
#pragma unroll
        for (int q = 0; q < NCH; q++) {
            if (q < qj) pl = f2max(pl, v[q]);
            if (q > qj) pr = f2max(pr, v[q]);
        }
        pl = f2max(pl, ((const float2*)(g_plp + (size_t)n * NH))[h2]);
        pr = f2max(pr, ((const float2*)(g_prp + (size_t)n * NH))[h2]);
        ((float2*)(g_pooled + (size_t)n * (2 * NH)))[h2] = pl;
        ((float2*)(g_pooled + (size_t)n * (2 * NH) + NH))[h2] = pr;
    }
}

// ---------------------------------------------------------------------------
// Kernel C: gemm with fused reduction. Block = (cand-oct, label-quad),
// 8 warps = K-splits of the SAME output tile; K-reduction completes in smem
// and writes out directly. Lane holds 8 A-float4 + 4 W-float4 per step.
// ---------------------------------------------------------------------------
__global__ __launch_bounds__(256) void k_gemm(const float* __restrict__ bias,
                                              float* __restrict__ out) {
    __shared__ float sp[SPLIT][32];
    int wid = threadIdx.x >> 5;     // K-split 0..7
    int lane = threadIdx.x & 31;
    int co = blockIdx.x;            // cand-oct 0..31
    int lq = blockIdx.y;            // label-quad 0..8
    int kbase = wid * KS;

    const float4* A = (const float4*)(g_pooled + (size_t)(co * 8) * (2 * NH) + kbase);
    const float4* Wt = (const float4*)(g_Wt + (size_t)(lq * 4) * (2 * NH) + kbase);
    const int rs = (2 * NH) / 4;

    float acc[8][4];
#pragma unroll
    for (int c = 0; c < 8; c++)
#pragma unroll
        for (int l = 0; l < 4; l++) acc[c][l] = 0.f;

#pragma unroll
    for (int step = 0; step < KS / 128; step++) {
        int i = lane + step * 32;
        float4 a[8], w[4];
#pragma unroll
        for (int c = 0; c < 8; c++) a[c] = A[c * rs + i];
#pragma unroll
        for (int l = 0; l < 4; l++) w[l] = Wt[l * rs + i];
#pragma unroll
        for (int c = 0; c < 8; c++)
#pragma unroll
            for (int l = 0; l < 4; l++) {
                acc[c][l] += a[c].x * w[l].x;
                acc[c][l] += a[c].y * w[l].y;
                acc[c][l] += a[c].z * w[l].z;
                acc[c][l] += a[c].w * w[l].w;
            }
    }

#pragma unroll
    for (int c = 0; c < 8; c++)
#pragma unroll
        for (int l = 0; l < 4; l++) {
            float s = acc[c][l];
#pragma unroll
            for (int o = 16; o; o >>= 1) s += __shfl_xor_sync(0xffffffffu, s, o);
            if (lane == 0) sp[wid][c * 4 + l] = s;
        }
    __syncthreads();

    if (threadIdx.x < 32) {
        int c = threadIdx.x >> 2;
        int l = threadIdx.x & 3;
        int label = lq * 4 + l;
        if (label < NL) {
            float s = bias[label];
#pragma unroll
            for (int w = 0; w < SPLIT; w++) s += sp[w][threadIdx.x];
            out[(size_t)(co * 8 + c) * NL + label] = s;
        }
    }
}

// ---------------------------------------------------------------------------
extern "C" void kernel_launch(void* const* d_in, const int* in_sizes, int n_in,
                              void* d_out, int out_size) {
    const float* hidden = (const float*)d_in[0];
    const float* W = (const float*)d_in[1];
    const float* bias = (const float*)d_in[2];
    const int* cb = (const int*)d_in[3];
    const int* cc = (const int*)d_in[4];
    float* out = (float*)d_out;

    k_A<<<CMB + WTB, 256>>>(hidden, W, cb, cc);

    k_scan_combine<<<NB * 2, 256>>>(cb, cc);

    dim3 gC(32, 9);
    k_gemm<<<gC, 256>>>(bias, out);
}